// round 1
// baseline (speedup 1.0000x reference)
#include <cuda_runtime.h>

#define POOL 7
#define NROI 32
#define NB   8
#define NC   1024
#define IMG_W 64
#define IMG_H 64

__device__ __forceinline__ float lerp2(float a, float b, float w) {
    return a + (b - a) * w;
}

__global__ __launch_bounds__(256, 8)
void roi_align_kernel(const float* __restrict__ img,
                      const int*   __restrict__ rois,
                      float*       __restrict__ out) {
    // block index decomposition: flat = ((r*NB + b)*POOL + py)*POOL + px
    int blk = blockIdx.x;
    int r   = blk / (NB * POOL * POOL);
    int rem = blk - r * (NB * POOL * POOL);
    int b   = rem / (POOL * POOL);
    int pp  = rem - b * (POOL * POOL);
    int py  = pp / POOL;
    int px  = pp - py * POOL;

    // roi: x, y, w, h
    const int4 roi = __ldg((const int4*)rois + r);

    float cx = ((float)px + 0.5f) * ((float)roi.z / (float)POOL) - 0.5f;
    float cy = ((float)py + 0.5f) * ((float)roi.w / (float)POOL) - 0.5f;
    float fx = floorf(cx);
    float fy = floorf(cy);
    int lox = max((int)fx, 0);
    int loy = max((int)fy, 0);
    int hix = min(max((int)ceilf(cx), 0), roi.z - 1);
    int hiy = min(max((int)ceilf(cy), 0), roi.w - 1);
    float wx = cx - fx;
    float wy = cy - fy;

    int X0 = roi.x + lox, X1 = roi.x + hix;
    int Y0 = roi.y + loy, Y1 = roi.y + hiy;

    const size_t ibase = (size_t)b * (IMG_H * IMG_W * NC);
    const float4* p00 = (const float4*)(img + ibase + ((size_t)(Y0 * IMG_W + X0)) * NC);
    const float4* p01 = (const float4*)(img + ibase + ((size_t)(Y0 * IMG_W + X1)) * NC);
    const float4* p10 = (const float4*)(img + ibase + ((size_t)(Y1 * IMG_W + X0)) * NC);
    const float4* p11 = (const float4*)(img + ibase + ((size_t)(Y1 * IMG_W + X1)) * NC);
    float4* po = (float4*)(out + (size_t)blk * NC);

    int t = threadIdx.x;  // 0..255 -> channel group
    float4 v00 = __ldg(p00 + t);
    float4 v01 = __ldg(p01 + t);
    float4 v10 = __ldg(p10 + t);
    float4 v11 = __ldg(p11 + t);

    float4 o;
    {
        float top = lerp2(v00.x, v01.x, wx);
        float bot = lerp2(v10.x, v11.x, wx);
        o.x = lerp2(top, bot, wy);
    }
    {
        float top = lerp2(v00.y, v01.y, wx);
        float bot = lerp2(v10.y, v11.y, wx);
        o.y = lerp2(top, bot, wy);
    }
    {
        float top = lerp2(v00.z, v01.z, wx);
        float bot = lerp2(v10.z, v11.z, wx);
        o.z = lerp2(top, bot, wy);
    }
    {
        float top = lerp2(v00.w, v01.w, wx);
        float bot = lerp2(v10.w, v11.w, wx);
        o.w = lerp2(top, bot, wy);
    }
    po[t] = o;
}

extern "C" void kernel_launch(void* const* d_in, const int* in_sizes, int n_in,
                              void* d_out, int out_size) {
    const float* img  = (const float*)d_in[0];
    const int*   rois = (const int*)d_in[1];
    // Defensive: metadata order should be img (33.5M elems) then rois (128),
    // but swap if the sizes say otherwise.
    if (n_in >= 2 && in_sizes[0] == NROI * 4) {
        img  = (const float*)d_in[1];
        rois = (const int*)d_in[0];
    }
    float* out = (float*)d_out;

    dim3 grid(NROI * NB * POOL * POOL);  // 12544
    dim3 block(256);
    roi_align_kernel<<<grid, block>>>(img, rois, out);
}

// round 2
// speedup vs baseline: 1.1275x; 1.1275x over previous
#include <cuda_runtime.h>

#define POOL 7
#define NROI 32
#define NB   8
#define NC   1024
#define IMG_W 64
#define IMG_H 64
#define PP   (POOL * POOL)

__device__ __forceinline__ float lerp2(float a, float b, float w) {
    return a + (b - a) * w;
}

__global__ __launch_bounds__(256, 8)
void roi_align_kernel(const float* __restrict__ img,
                      const int*   __restrict__ rois,
                      float*       __restrict__ out) {
    // Batch-major block order for L2 locality:
    //   blk = ((b * NROI) + r) * PP + pp
    // so each concurrent wave works on ONE batch's image slice (~16MB, L2-resident).
    int blk = blockIdx.x;
    int b   = blk / (NROI * PP);
    int rem = blk - b * (NROI * PP);
    int r   = rem / PP;
    int pp  = rem - r * PP;
    int py  = pp / POOL;
    int px  = pp - py * POOL;

    // roi: x, y, w, h
    const int4 roi = __ldg((const int4*)rois + r);

    float cx = ((float)px + 0.5f) * ((float)roi.z / (float)POOL) - 0.5f;
    float cy = ((float)py + 0.5f) * ((float)roi.w / (float)POOL) - 0.5f;
    float fx = floorf(cx);
    float fy = floorf(cy);
    int lox = max((int)fx, 0);
    int loy = max((int)fy, 0);
    int hix = min(max((int)ceilf(cx), 0), roi.z - 1);
    int hiy = min(max((int)ceilf(cy), 0), roi.w - 1);
    float wx = cx - fx;
    float wy = cy - fy;

    int X0 = roi.x + lox, X1 = roi.x + hix;
    int Y0 = roi.y + loy, Y1 = roi.y + hiy;

    const size_t ibase = (size_t)b * (IMG_H * IMG_W * NC);
    const float4* p00 = (const float4*)(img + ibase + ((size_t)(Y0 * IMG_W + X0)) * NC);
    const float4* p01 = (const float4*)(img + ibase + ((size_t)(Y0 * IMG_W + X1)) * NC);
    const float4* p10 = (const float4*)(img + ibase + ((size_t)(Y1 * IMG_W + X0)) * NC);
    const float4* p11 = (const float4*)(img + ibase + ((size_t)(Y1 * IMG_W + X1)) * NC);

    // Output layout is (r, b, py, px, c) flattened.
    size_t oidx = (((size_t)r * NB + b) * PP + pp) * NC;
    float4* po = (float4*)(out + oidx);

    int t = threadIdx.x;  // 0..255 -> channel group of 4 floats
    float4 v00 = __ldg(p00 + t);
    float4 v01 = __ldg(p01 + t);
    float4 v10 = __ldg(p10 + t);
    float4 v11 = __ldg(p11 + t);

    float4 o;
    {
        float top = lerp2(v00.x, v01.x, wx);
        float bot = lerp2(v10.x, v11.x, wx);
        o.x = lerp2(top, bot, wy);
    }
    {
        float top = lerp2(v00.y, v01.y, wx);
        float bot = lerp2(v10.y, v11.y, wx);
        o.y = lerp2(top, bot, wy);
    }
    {
        float top = lerp2(v00.z, v01.z, wx);
        float bot = lerp2(v10.z, v11.z, wx);
        o.z = lerp2(top, bot, wy);
    }
    {
        float top = lerp2(v00.w, v01.w, wx);
        float bot = lerp2(v10.w, v11.w, wx);
        o.w = lerp2(top, bot, wy);
    }
    // Streaming store: output is write-once, keep it from evicting img in L2.
    __stcs(po + t, o);
}

extern "C" void kernel_launch(void* const* d_in, const int* in_sizes, int n_in,
                              void* d_out, int out_size) {
    const float* img  = (const float*)d_in[0];
    const int*   rois = (const int*)d_in[1];
    if (n_in >= 2 && in_sizes[0] == NROI * 4) {
        img  = (const float*)d_in[1];
        rois = (const int*)d_in[0];
    }
    float* out = (float*)d_out;

    dim3 grid(NROI * NB * PP);  // 12544
    dim3 block(256);
    roi_align_kernel<<<grid, block>>>(img, rois, out);
}